// round 10
// baseline (speedup 1.0000x reference)
#include <cuda_runtime.h>
#include <cuda_fp16.h>
#include <cstdint>

#define N_NODES 100000
#define N_EDGES 1250000
#define D_IN 32
#define H 64
#define SCAN_B 1024
#define NB ((N_NODES + SCAN_B - 1) / SCAN_B)   // 98
#define NPW 8                                   // nodes per warp
#define MLPB ((N_NODES + 8 * NPW - 1) / (8 * NPW))   // 1563 blocks

// scratch
__device__ __half g_hh[(size_t)N_NODES * H];    // fp16 copy of h (gather source)
__device__ int    g_deg[N_NODES];
__device__ int    g_off[N_NODES + 1];
__device__ int    g_pos[N_NODES];
__device__ int    g_csr_col[N_EDGES];
__device__ int    g_flag[NB];                   // decoupled-lookback: agg+1 (0 = not ready)

// ---- packed f32x2 helpers (sm_103a dual-FMA) --------------------------------
__device__ __forceinline__ unsigned long long pk2(float lo, float hi) {
    unsigned long long r;
    asm("mov.b64 %0, {%1, %2};" : "=l"(r) : "f"(lo), "f"(hi));
    return r;
}
__device__ __forceinline__ void upk2(unsigned long long v, float& lo, float& hi) {
    asm("mov.b64 {%0, %1}, %2;" : "=f"(lo), "=f"(hi) : "l"(v));
}
__device__ __forceinline__ void fma2(unsigned long long& d, unsigned long long a,
                                     unsigned long long b) {
    asm("fma.rn.f32x2 %0, %1, %2, %0;" : "+l"(d) : "l"(a), "l"(b));
}

// ---------------------------------------------------------------------------
// K1: fused node MLP, 8 nodes/warp, k-pair FFMA2.
// Writes h fp32 -> out (exact self term) and h fp16 -> g_hh (gather source).
// ---------------------------------------------------------------------------
__global__ __launch_bounds__(256) void mlp_kernel(
    const float* __restrict__ x,
    const float* __restrict__ W1, const float* __restrict__ b1,
    const float* __restrict__ g1, const float* __restrict__ be1,
    const float* __restrict__ W2, const float* __restrict__ b2,
    const float* __restrict__ g2, const float* __restrict__ be2,
    float* __restrict__ out)
{
    const int tid = threadIdx.x;

    __shared__ __align__(16) unsigned long long sW1p[(D_IN / 2) * H];   // 8 KB
    __shared__ __align__(16) unsigned long long sW2p[(H / 2) * H];      // 16 KB
    __shared__ float sb1[H], sg1[H], sbe1[H];
    __shared__ float sb2[H], sg2[H], sbe2[H];
    __shared__ __align__(16) float sx[8][NPW][D_IN];   // 8 KB
    __shared__ __align__(16) float sh[8][NPW][H];      // 16 KB

    {
        float* w1f = (float*)sW1p;
        float* w2f = (float*)sW2p;
        for (int i = tid; i < D_IN * H; i += 256) {
            int k = i >> 6, d = i & 63;
            w1f[((k >> 1) * 64 + d) * 2 + (k & 1)] = W1[i];
        }
        for (int i = tid; i < H * H; i += 256) {
            int k = i >> 6, d = i & 63;
            w2f[((k >> 1) * 64 + d) * 2 + (k & 1)] = W2[i];
        }
    }
    if (tid < H) {
        sb1[tid] = b1[tid]; sg1[tid] = g1[tid]; sbe1[tid] = be1[tid];
        sb2[tid] = b2[tid]; sg2[tid] = g2[tid]; sbe2[tid] = be2[tid];
    }
    __syncthreads();

    const int warp = tid >> 5;
    const int lane = tid & 31;
    const int n0 = (blockIdx.x * 8 + warp) * NPW;
    if (n0 >= N_NODES) return;

    #pragma unroll
    for (int j = 0; j < NPW; j++) {
        const int nj = min(n0 + j, N_NODES - 1);      // clamp (tail-safe)
        sx[warp][j][lane] = x[(size_t)nj * D_IN + lane];
    }
    __syncwarp();

    // ---- layer 1 ----
    unsigned long long a0[NPW], a1[NPW];
    #pragma unroll
    for (int j = 0; j < NPW; j++) {
        a0[j] = pk2(sb1[lane],      0.0f);
        a1[j] = pk2(sb1[lane + 32], 0.0f);
    }
    #pragma unroll
    for (int kp2 = 0; kp2 < D_IN / 4; kp2++) {
        const unsigned long long w0a = sW1p[(2 * kp2)     * 64 + lane];
        const unsigned long long w1a = sW1p[(2 * kp2)     * 64 + lane + 32];
        const unsigned long long w0b = sW1p[(2 * kp2 + 1) * 64 + lane];
        const unsigned long long w1b = sW1p[(2 * kp2 + 1) * 64 + lane + 32];
        #pragma unroll
        for (int j = 0; j < NPW; j++) {
            const double2 xd = *(const double2*)&sx[warp][j][kp2 * 4];
            const unsigned long long xlo = __double_as_longlong(xd.x);
            const unsigned long long xhi = __double_as_longlong(xd.y);
            fma2(a0[j], xlo, w0a);
            fma2(a1[j], xlo, w1a);
            fma2(a0[j], xhi, w0b);
            fma2(a1[j], xhi, w1b);
        }
    }
    #pragma unroll
    for (int g = 0; g < NPW; g += 4) {
        float s[4], q[4], v0[4], v1[4];
        #pragma unroll
        for (int u = 0; u < 4; u++) {
            float l0, h0, l1, h1;
            upk2(a0[g + u], l0, h0); upk2(a1[g + u], l1, h1);
            v0[u] = l0 + h0; v1[u] = l1 + h1;
            s[u] = v0[u] + v1[u];
            q[u] = v0[u] * v0[u] + v1[u] * v1[u];
        }
        #pragma unroll
        for (int off = 16; off > 0; off >>= 1) {
            #pragma unroll
            for (int u = 0; u < 4; u++) {
                s[u] += __shfl_xor_sync(0xffffffffu, s[u], off);
                q[u] += __shfl_xor_sync(0xffffffffu, q[u], off);
            }
        }
        #pragma unroll
        for (int u = 0; u < 4; u++) {
            const float mu  = s[u] * (1.0f / H);
            const float var = q[u] * (1.0f / H) - mu * mu;
            const float inv = rsqrtf(var + 1e-5f);
            float r0 = (v0[u] - mu) * inv * sg1[lane]      + sbe1[lane];
            float r1 = (v1[u] - mu) * inv * sg1[lane + 32] + sbe1[lane + 32];
            sh[warp][g + u][lane]      = fmaxf(r0, 0.0f);
            sh[warp][g + u][lane + 32] = fmaxf(r1, 0.0f);
        }
    }
    __syncwarp();

    // ---- layer 2 ----
    unsigned long long c0[NPW], c1[NPW];
    #pragma unroll
    for (int j = 0; j < NPW; j++) {
        c0[j] = pk2(sb2[lane],      0.0f);
        c1[j] = pk2(sb2[lane + 32], 0.0f);
    }
    #pragma unroll
    for (int kp2 = 0; kp2 < H / 4; kp2++) {
        const unsigned long long w0a = sW2p[(2 * kp2)     * 64 + lane];
        const unsigned long long w1a = sW2p[(2 * kp2)     * 64 + lane + 32];
        const unsigned long long w0b = sW2p[(2 * kp2 + 1) * 64 + lane];
        const unsigned long long w1b = sW2p[(2 * kp2 + 1) * 64 + lane + 32];
        #pragma unroll
        for (int j = 0; j < NPW; j++) {
            const double2 hd = *(const double2*)&sh[warp][j][kp2 * 4];
            const unsigned long long hlo = __double_as_longlong(hd.x);
            const unsigned long long hhi = __double_as_longlong(hd.y);
            fma2(c0[j], hlo, w0a);
            fma2(c1[j], hlo, w1a);
            fma2(c0[j], hhi, w0b);
            fma2(c1[j], hhi, w1b);
        }
    }
    #pragma unroll
    for (int g = 0; g < NPW; g += 4) {
        float s[4], q[4], v0[4], v1[4];
        #pragma unroll
        for (int u = 0; u < 4; u++) {
            float l0, h0, l1, h1;
            upk2(c0[g + u], l0, h0); upk2(c1[g + u], l1, h1);
            v0[u] = l0 + h0; v1[u] = l1 + h1;
            s[u] = v0[u] + v1[u];
            q[u] = v0[u] * v0[u] + v1[u] * v1[u];
        }
        #pragma unroll
        for (int off = 16; off > 0; off >>= 1) {
            #pragma unroll
            for (int u = 0; u < 4; u++) {
                s[u] += __shfl_xor_sync(0xffffffffu, s[u], off);
                q[u] += __shfl_xor_sync(0xffffffffu, q[u], off);
            }
        }
        #pragma unroll
        for (int u = 0; u < 4; u++) {
            const int nj = n0 + g + u;
            if (nj < N_NODES) {
                const float mu  = s[u] * (1.0f / H);
                const float var = q[u] * (1.0f / H) - mu * mu;
                const float inv = rsqrtf(var + 1e-5f);
                float r0 = (v0[u] - mu) * inv * sg2[lane]      + sbe2[lane];
                float r1 = (v1[u] - mu) * inv * sg2[lane + 32] + sbe2[lane + 32];
                r0 = fmaxf(r0, 0.0f);
                r1 = fmaxf(r1, 0.0f);
                const size_t base = (size_t)nj * H;
                out[base + lane]       = r0;               // exact self term
                out[base + lane + 32]  = r1;
                g_hh[base + lane]      = __float2half(r0); // fp16 gather source
                g_hh[base + lane + 32] = __float2half(r1);
            }
        }
    }
}

// ---------------------------------------------------------------------------
// K2b: degree histogram (4 edges/thread, int4 loads, fire-and-forget atomics)
// ---------------------------------------------------------------------------
__global__ __launch_bounds__(256) void hist_kernel(const int* __restrict__ ei)
{
    const int e4 = (blockIdx.x * 256 + threadIdx.x) * 4;
    if (e4 >= N_EDGES) return;
    const int4 rows = *(const int4*)&ei[e4];
    #pragma unroll
    for (int j = 0; j < 4; j++) {
        const int row = (&rows.x)[j];
        if ((unsigned)row < N_NODES) atomicAdd(&g_deg[row], 1);
    }
}

// ---------------------------------------------------------------------------
// K3b: single-kernel exclusive scan (decoupled lookback; 98 blocks all wave-1)
// ---------------------------------------------------------------------------
__global__ __launch_bounds__(SCAN_B) void scan_kernel()
{
    __shared__ int wsum[32];
    __shared__ int sprefix;
    const int t   = threadIdx.x;
    const int bid = blockIdx.x;
    const int i   = bid * SCAN_B + t;

    int v = (i < N_NODES) ? g_deg[i] : 0;
    const int orig = v;
    #pragma unroll
    for (int o = 1; o < 32; o <<= 1) {
        int n = __shfl_up_sync(0xffffffffu, v, o);
        if ((t & 31) >= o) v += n;
    }
    if ((t & 31) == 31) wsum[t >> 5] = v;
    __syncthreads();
    if (t < 32) {
        int w = wsum[t];
        #pragma unroll
        for (int o = 1; o < 32; o <<= 1) {
            int n = __shfl_up_sync(0xffffffffu, w, o);
            if (t >= o) w += n;
        }
        wsum[t] = w;
    }
    __syncthreads();
    const int base = (t >= 32) ? wsum[(t >> 5) - 1] : 0;
    const int incl = v + base;

    if (t == SCAN_B - 1) ((volatile int*)g_flag)[bid] = incl + 1;

    if (t < 32) {
        int sum = 0;
        for (int j0 = bid - 1; j0 >= 0; j0 -= 32) {
            const int j = j0 - t;
            int av = 0;
            if (j >= 0) {
                while ((av = ((volatile int*)g_flag)[j]) == 0) {}
                av -= 1;
            }
            #pragma unroll
            for (int o = 16; o > 0; o >>= 1)
                av += __shfl_xor_sync(0xffffffffu, av, o);
            sum += av;
        }
        if (t == 0) sprefix = sum;
    }
    __syncthreads();

    if (i < N_NODES) {
        const int o = sprefix + incl - orig;
        g_off[i] = o;
        g_pos[i] = o;
    }
    if (i == 0) g_off[N_NODES] = N_EDGES;
}

// ---------------------------------------------------------------------------
// K4b: scatter column ids into CSR slots (4 edges/thread, int4 index loads)
// ---------------------------------------------------------------------------
__global__ __launch_bounds__(256) void scatter_kernel(const int* __restrict__ ei)
{
    const int e4 = (blockIdx.x * 256 + threadIdx.x) * 4;
    if (e4 >= N_EDGES) return;
    const int4 rows = *(const int4*)&ei[e4];
    const int4 cols = *(const int4*)&ei[N_EDGES + e4];
    #pragma unroll
    for (int j = 0; j < 4; j++) {
        const int row = (&rows.x)[j];
        const int col = (&cols.x)[j];
        if ((unsigned)row < N_NODES) {
            int p = atomicAdd(&g_pos[row], 1);
            g_csr_col[p] = col;
        }
    }
}

// ---------------------------------------------------------------------------
// K5: pull-gather, warp per node, fp16 neighbor rows (8B/lane = 4 dims),
// 2 edges in flight per warp. Self term read fp32 from out, result -> out.
// ---------------------------------------------------------------------------
__global__ __launch_bounds__(256) void gather_kernel(float* __restrict__ out)
{
    const int n = blockIdx.x * 8 + (threadIdx.x >> 5);
    if (n >= N_NODES) return;
    const int lane = threadIdx.x & 31;
    const int half = lane >> 4;
    const int hl   = lane & 15;

    float4 acc = make_float4(0.f, 0.f, 0.f, 0.f);

    const int start = g_off[n];
    const int end   = g_off[n + 1];

    for (int jb = start; jb < end; jb += 32) {
        const int cnt = min(32, end - jb);
        int cidx = (lane < cnt) ? g_csr_col[jb + lane] : 0;
        const int iters = (cnt + 1) >> 1;
        for (int it = 0; it < iters; it++) {
            const int tt = 2 * it + half;
            const int cc = __shfl_sync(0xffffffffu, cidx, tt & 31);
            if (tt < cnt) {
                const uint2 u = __ldg((const uint2*)(g_hh + (size_t)cc * H) + hl);
                const float2 f01 = __half22float2(*(const half2*)&u.x);
                const float2 f23 = __half22float2(*(const half2*)&u.y);
                acc.x += f01.x; acc.y += f01.y; acc.z += f23.x; acc.w += f23.y;
            }
        }
    }

    acc.x += __shfl_down_sync(0xffffffffu, acc.x, 16);
    acc.y += __shfl_down_sync(0xffffffffu, acc.y, 16);
    acc.z += __shfl_down_sync(0xffffffffu, acc.z, 16);
    acc.w += __shfl_down_sync(0xffffffffu, acc.w, 16);

    if (lane < 16) {
        float4* op = (float4*)out + (size_t)n * 16 + hl;
        const float4 self = *op;                       // exact fp32 self term
        acc.x += self.x; acc.y += self.y; acc.z += self.z; acc.w += self.w;
        *op = acc;
    }
}

// ---------------------------------------------------------------------------
// inputs: x, edge_index(int32 [2,E]), W1, b1, g1, beta1, W2, b2, g2, beta2
// Two-stream fork inside graph capture: MLP on capture stream, CSR build on s2.
// ---------------------------------------------------------------------------
extern "C" void kernel_launch(void* const* d_in, const int* in_sizes, int n_in,
                              void* d_out, int out_size)
{
    const float* x   = (const float*)d_in[0];
    const int*   ei  = (const int*)d_in[1];
    const float* W1  = (const float*)d_in[2];
    const float* b1  = (const float*)d_in[3];
    const float* g1  = (const float*)d_in[4];
    const float* be1 = (const float*)d_in[5];
    const float* W2  = (const float*)d_in[6];
    const float* b2  = (const float*)d_in[7];
    const float* g2  = (const float*)d_in[8];
    const float* be2 = (const float*)d_in[9];
    float* out = (float*)d_out;

    static cudaStream_t s2 = nullptr;
    static cudaEvent_t evFork = nullptr, evJoin = nullptr;
    static void* p_deg = nullptr;
    static void* p_flag = nullptr;
    if (!s2) {
        cudaStreamCreateWithFlags(&s2, cudaStreamNonBlocking);
        cudaEventCreateWithFlags(&evFork, cudaEventDisableTiming);
        cudaEventCreateWithFlags(&evJoin, cudaEventDisableTiming);
        cudaGetSymbolAddress(&p_deg,  g_deg);
        cudaGetSymbolAddress(&p_flag, g_flag);
    }

    cudaEventRecord(evFork, 0);
    cudaStreamWaitEvent(s2, evFork, 0);

    cudaMemsetAsync(p_deg,  0, sizeof(int) * N_NODES, s2);
    cudaMemsetAsync(p_flag, 0, sizeof(int) * NB, s2);
    hist_kernel<<<(N_EDGES / 4 + 255) / 256, 256, 0, s2>>>(ei);
    scan_kernel<<<NB, SCAN_B, 0, s2>>>();
    scatter_kernel<<<(N_EDGES / 4 + 255) / 256, 256, 0, s2>>>(ei);
    cudaEventRecord(evJoin, s2);

    mlp_kernel<<<MLPB, 256>>>(x, W1, b1, g1, be1, W2, b2, g2, be2, out);

    cudaStreamWaitEvent(0, evJoin, 0);
    gather_kernel<<<(N_NODES + 7) / 8, 256>>>(out);
}